// round 5
// baseline (speedup 1.0000x reference)
#include <cuda_runtime.h>
#include <cuda_bf16.h>
#include <cstdint>

// ---------------- problem constants ----------------
#define M_SZ 32768
#define H_SZ 512
#define K_SZ 1024
#define NKC  32            // k32 chunks

#define SWZ(x) ((uint32_t)(x) ^ ((((uint32_t)(x)) >> 3) & 0x70))

// packed split layout: row = 32 chunks x [hi 64B | lo 64B] = 4KB per row
__device__ unsigned char g_A[(size_t)M_SZ * 4096];        // 128MB
__device__ unsigned char g_B[(size_t)3 * H_SZ * 4096];    // 6MB

// ---------------- helpers ----------------
__device__ __forceinline__ uint32_t smem_u32(const void* p) {
    uint32_t a;
    asm("{ .reg .u64 t; cvta.to.shared.u64 t, %1; cvt.u32.u64 %0, t; }" : "=r"(a) : "l"(p));
    return a;
}
__device__ __forceinline__ void cpa16(uint32_t d, const void* s) {
    asm volatile("cp.async.cg.shared.global [%0], [%1], 16;" :: "r"(d), "l"(s));
}
__device__ __forceinline__ void ldmx4(uint32_t* r, uint32_t a) {
    asm volatile("ldmatrix.sync.aligned.m8n8.x4.shared.b16 {%0,%1,%2,%3}, [%4];"
        : "=r"(r[0]), "=r"(r[1]), "=r"(r[2]), "=r"(r[3]) : "r"(a));
}
__device__ __forceinline__ void mma16816(float* c, const uint32_t* a, uint32_t b0, uint32_t b1) {
    asm volatile("mma.sync.aligned.m16n8k16.row.col.f32.bf16.bf16.f32 "
        "{%0,%1,%2,%3}, {%4,%5,%6,%7}, {%8,%9}, {%0,%1,%2,%3};"
        : "+f"(c[0]), "+f"(c[1]), "+f"(c[2]), "+f"(c[3])
        : "r"(a[0]), "r"(a[1]), "r"(a[2]), "r"(a[3]), "r"(b0), "r"(b1));
}

// ---------------- prep A: fp32 -> packed bf16 hi/lo ----------------
__global__ __launch_bounds__(256)
void prep_a(const float* __restrict__ x, const float* __restrict__ h) {
    int gid = blockIdx.x * 256 + threadIdx.x;
    int m = gid >> 8;
    int k4 = (gid & 255) << 2;
    const float* src = (k4 < 512) ? (x + (size_t)m * 512 + k4)
                                  : (h + (size_t)m * 512 + (k4 - 512));
    float4 v = *(const float4*)src;
    float vv[4] = {v.x, v.y, v.z, v.w};
    __nv_bfloat16 hi[4], lo[4];
    #pragma unroll
    for (int i = 0; i < 4; ++i) {
        hi[i] = __float2bfloat16(vv[i]);
        lo[i] = __float2bfloat16(vv[i] - __bfloat162float(hi[i]));
    }
    unsigned char* dst = g_A + (size_t)m * 4096 + (k4 >> 5) * 128 + (k4 & 31) * 2;
    *(uint2*)dst        = *(uint2*)hi;
    *(uint2*)(dst + 64) = *(uint2*)lo;
}

// ---------------- prep B: transpose + packed hi/lo ----------------
__global__ void prep_b(const float* __restrict__ Wxi, const float* __restrict__ Whi,
                       const float* __restrict__ Wxc, const float* __restrict__ Whc,
                       const float* __restrict__ Wxo, const float* __restrict__ Who) {
    __shared__ float tile[32][33];
    int n0 = blockIdx.x * 32;       // 0..1535
    int k0 = blockIdx.y * 32;       // 0..1023
    int g = n0 >> 9;
    int nc0 = n0 & 511;
    const float* Wx = (g == 0) ? Wxi : ((g == 1) ? Wxc : Wxo);
    const float* Wh = (g == 0) ? Whi : ((g == 1) ? Whc : Who);
    int tx = threadIdx.x, ty = threadIdx.y;   // 32 x 8
    #pragma unroll
    for (int r = ty; r < 32; r += 8) {
        int k = k0 + r;
        const float* W = (k < 512) ? (Wx + (size_t)k * 512) : (Wh + (size_t)(k - 512) * 512);
        tile[r][tx] = W[nc0 + tx];
    }
    __syncthreads();
    #pragma unroll
    for (int r = ty; r < 32; r += 8) {
        float v = tile[tx][r];                     // W[k0+tx][n0+r]
        __nv_bfloat16 hi = __float2bfloat16(v);
        __nv_bfloat16 lo = __float2bfloat16(v - __bfloat162float(hi));
        int k = k0 + tx;
        unsigned char* dst = g_B + (size_t)(n0 + r) * 4096 + (k >> 5) * 128 + (k & 31) * 2;
        *(__nv_bfloat16*)dst        = hi;
        *(__nv_bfloat16*)(dst + 64) = lo;
    }
}

// ---------------- fused GEMM + epilogue ----------------
// CTA 128m x 128n x 3 gates; 256 threads = 8 warps (2m x 4n), warp 64x32/gate.
// Stage (k32): A 16KB (128 rows x [hi64|lo64]) + B 48KB (384 rows) = 64KB; 3 stages.
__global__ __launch_bounds__(256, 1)
void lstm_gemm(const float* __restrict__ bxi, const float* __restrict__ bxc,
               const float* __restrict__ bxo,
               float* __restrict__ outh, float* __restrict__ outc) {
    extern __shared__ char dsm[];
    const uint32_t s0 = (smem_u32(dsm) + 1023) & ~1023u;

    const int tid  = threadIdx.x;
    const int lane = tid & 31;
    const int wid  = tid >> 5;
    const int wm   = wid >> 2;       // 0..1 -> m offset 64*wm
    const int wn   = wid & 3;        // 0..3 -> n offset 32*wn
    const int m0   = blockIdx.y << 7;
    const int n0   = blockIdx.x << 7;

    // ldmatrix base offsets (split=0, ks=0); strides are swizzle-invariant
    uint32_t a_off0, b_off0[2];
    {
        int row = (wm << 6) + (lane & 15);
        int ro  = (row << 7) + ((lane >> 4) << 4);
        a_off0 = SWZ(ro);                                   // + mt*2048
    }
    #pragma unroll
    for (int ng = 0; ng < 2; ++ng) {
        int rr = (wn << 5) + (ng << 4) + (lane & 7) + (((lane >> 4) & 1) << 3);
        int ro = (rr << 7) + (((lane >> 3) & 1) << 4);
        b_off0[ng] = SWZ(ro);                               // + g*16384
    }

    float c[3][4][4][4];   // gate, mt, nt, e
    #pragma unroll
    for (int g = 0; g < 3; ++g)
        #pragma unroll
        for (int mt = 0; mt < 4; ++mt)
            #pragma unroll
            for (int nt = 0; nt < 4; ++nt)
                #pragma unroll
                for (int e = 0; e < 4; ++e) c[g][mt][nt][e] = 0.0f;

    // stage loader: 4096 x 16B (A:1024, B:3072), 16 per thread
    auto load_stage = [&](int s, int kc) {
        const uint32_t sa = s0 + (uint32_t)s * 65536u;
        const size_t kb = (size_t)kc * 128;
        #pragma unroll
        for (int i = 0; i < 16; ++i) {
            int gid = tid + 256 * i;
            if (gid < 1024) {
                int row = gid >> 3, grp = gid & 7;
                int ob = (row << 7) + (grp << 4);
                cpa16(sa + SWZ(ob),
                      g_A + (size_t)(m0 + row) * 4096 + kb + (grp << 4));
            } else {
                int t = gid - 1024;              // 0..3071
                int row = t >> 3, grp = t & 7;   // row: g*128+n
                int g = row >> 7, n = row & 127;
                int ob = (row << 7) + (grp << 4);
                cpa16(sa + 16384u + SWZ(ob),
                      g_B + (size_t)((g << 9) + n0 + n) * 4096 + kb + (grp << 4));
            }
        }
    };

    load_stage(0, 0);
    asm volatile("cp.async.commit_group;" ::: "memory");
    load_stage(1, 1);
    asm volatile("cp.async.commit_group;" ::: "memory");

    for (int kc = 0; kc < NKC; ++kc) {
        asm volatile("cp.async.wait_group 1;" ::: "memory");
        __syncthreads();
        if (kc + 2 < NKC) load_stage((kc + 2) % 3, kc + 2);
        asm volatile("cp.async.commit_group;" ::: "memory");

        const uint32_t sA = s0 + (uint32_t)(kc % 3) * 65536u;
        const uint32_t sB = sA + 16384u;

        #pragma unroll
        for (int ks = 0; ks < 2; ++ks) {
            const uint32_t kx = (uint32_t)(ks << 5);
            uint32_t af[4][4];
            // ---- Ah phase: Ah*Bh + Ah*Bl ----
            #pragma unroll
            for (int mt = 0; mt < 4; ++mt)
                ldmx4(af[mt], sA + ((a_off0 + mt * 2048) ^ kx));
            #pragma unroll
            for (int g = 0; g < 3; ++g) {
                #pragma unroll
                for (int ng = 0; ng < 2; ++ng) {
                    const uint32_t bb = sB + (uint32_t)(g << 14);
                    uint32_t bh[4], bl[4];
                    ldmx4(bh, bb + (b_off0[ng] ^ kx));
                    ldmx4(bl, bb + (b_off0[ng] ^ kx ^ 64u));
                    #pragma unroll
                    for (int mt = 0; mt < 4; ++mt) {
                        mma16816(c[g][mt][2*ng+0], af[mt], bh[0], bh[1]);
                        mma16816(c[g][mt][2*ng+1], af[mt], bh[2], bh[3]);
                        mma16816(c[g][mt][2*ng+0], af[mt], bl[0], bl[1]);
                        mma16816(c[g][mt][2*ng+1], af[mt], bl[2], bl[3]);
                    }
                }
            }
            // ---- Al phase: Al*Bh ----
            #pragma unroll
            for (int mt = 0; mt < 4; ++mt)
                ldmx4(af[mt], sA + ((a_off0 + mt * 2048) ^ kx ^ 64u));
            #pragma unroll
            for (int g = 0; g < 3; ++g) {
                #pragma unroll
                for (int ng = 0; ng < 2; ++ng) {
                    const uint32_t bb = sB + (uint32_t)(g << 14);
                    uint32_t bh[4];
                    ldmx4(bh, bb + (b_off0[ng] ^ kx));
                    #pragma unroll
                    for (int mt = 0; mt < 4; ++mt) {
                        mma16816(c[g][mt][2*ng+0], af[mt], bh[0], bh[1]);
                        mma16816(c[g][mt][2*ng+1], af[mt], bh[2], bh[3]);
                    }
                }
            }
        }
        __syncthreads();
    }

    // ---- fused epilogue ----
    const int ncb = n0 + (wn << 5) + ((lane & 3) << 1);
    float2 bi2[4], bc2[4], bo2[4];
    #pragma unroll
    for (int nt = 0; nt < 4; ++nt) {
        bi2[nt] = *(const float2*)(bxi + ncb + nt * 8);
        bc2[nt] = *(const float2*)(bxc + ncb + nt * 8);
        bo2[nt] = *(const float2*)(bxo + ncb + nt * 8);
    }

    #pragma unroll
    for (int mt = 0; mt < 4; ++mt) {
        #pragma unroll
        for (int half = 0; half < 2; ++half) {
            int m = m0 + (wm << 6) + (mt << 4) + (lane >> 2) + half * 8;
            size_t ob = (size_t)m * 512;
            #pragma unroll
            for (int nt = 0; nt < 4; ++nt) {
                float hv[2], cv[2];
                #pragma unroll
                for (int e = 0; e < 2; ++e) {
                    int idx = half * 2 + e;
                    float ip = c[0][mt][nt][idx] + (e ? bi2[nt].y : bi2[nt].x);
                    float cp = c[1][mt][nt][idx] + (e ? bc2[nt].y : bc2[nt].x);
                    float op = c[2][mt][nt][idx] + (e ? bo2[nt].y : bo2[nt].x);
                    float ig = 1.0f / (1.0f + __expf(-ip));
                    float og = 1.0f / (1.0f + __expf(-op));
                    float tc = 1.0f - 2.0f / (__expf(2.0f * cp) + 1.0f);
                    float cn = ig * tc;
                    float tn = 1.0f - 2.0f / (__expf(2.0f * cn) + 1.0f);
                    cv[e] = cn;
                    hv[e] = og * tn;
                }
                *(float2*)(outh + ob + ncb + nt * 8) = *(float2*)hv;
                *(float2*)(outc + ob + ncb + nt * 8) = *(float2*)cv;
            }
        }
    }
}

// ---------------- launcher ----------------
extern "C" void kernel_launch(void* const* d_in, const int* in_sizes, int n_in,
                              void* d_out, int out_size) {
    // 0:x 1:h 2:c_prev 3:Wxi 4:bxi 5:Whi 6:Wxf 7:bxf 8:Whf 9:Wxc 10:bxc 11:Whc 12:Wxo 13:bxo 14:Who
    const float* x   = (const float*)d_in[0];
    const float* h   = (const float*)d_in[1];
    const float* Wxi = (const float*)d_in[3];
    const float* bxi = (const float*)d_in[4];
    const float* Whi = (const float*)d_in[5];
    const float* Wxc = (const float*)d_in[9];
    const float* bxc = (const float*)d_in[10];
    const float* Whc = (const float*)d_in[11];
    const float* Wxo = (const float*)d_in[12];
    const float* bxo = (const float*)d_in[13];
    const float* Who = (const float*)d_in[14];

    float* outh = (float*)d_out;
    float* outc = outh + (size_t)M_SZ * H_SZ;

    cudaFuncSetAttribute(lstm_gemm, cudaFuncAttributeMaxDynamicSharedMemorySize,
                         3 * 65536 + 1024);

    prep_a<<<32768, 256>>>(x, h);
    prep_b<<<dim3(48, 32), dim3(32, 8)>>>(Wxi, Whi, Wxc, Whc, Wxo, Who);
    lstm_gemm<<<dim3(4, 256), 256, 3 * 65536 + 1024>>>(bxi, bxc, bxo, outh, outc);
}

// round 6
// speedup vs baseline: 1.3462x; 1.3462x over previous
#include <cuda_runtime.h>
#include <cuda_fp16.h>
#include <cstdint>

// ---------------- problem constants ----------------
#define M_SZ 32768
#define H_SZ 512
#define K_SZ 1024
#define NKC  32            // k32 chunks

#define SWZ(x)   ((uint32_t)(x) ^ ((((uint32_t)(x)) >> 3) & 0x70))
#define SWZ64(x) ((uint32_t)(x) ^ ((((uint32_t)(x)) >> 3) & 0x30))

// A: plain fp16 [m][k], 2KB/row.  B: [gate*512+n] rows of 32 chunks x [hi64|lo64] = 4KB/row
__device__ unsigned char g_A[(size_t)M_SZ * 2048];        // 64MB
__device__ unsigned char g_B[(size_t)3 * H_SZ * 4096];    // 6MB

// ---------------- helpers ----------------
__device__ __forceinline__ uint32_t smem_u32(const void* p) {
    uint32_t a;
    asm("{ .reg .u64 t; cvta.to.shared.u64 t, %1; cvt.u32.u64 %0, t; }" : "=r"(a) : "l"(p));
    return a;
}
__device__ __forceinline__ void cpa16(uint32_t d, const void* s) {
    asm volatile("cp.async.cg.shared.global [%0], [%1], 16;" :: "r"(d), "l"(s));
}
__device__ __forceinline__ void ldmx4(uint32_t* r, uint32_t a) {
    asm volatile("ldmatrix.sync.aligned.m8n8.x4.shared.b16 {%0,%1,%2,%3}, [%4];"
        : "=r"(r[0]), "=r"(r[1]), "=r"(r[2]), "=r"(r[3]) : "r"(a));
}
__device__ __forceinline__ void mma16816(float* c, const uint32_t* a, uint32_t b0, uint32_t b1) {
    asm volatile("mma.sync.aligned.m16n8k16.row.col.f32.f16.f16.f32 "
        "{%0,%1,%2,%3}, {%4,%5,%6,%7}, {%8,%9}, {%0,%1,%2,%3};"
        : "+f"(c[0]), "+f"(c[1]), "+f"(c[2]), "+f"(c[3])
        : "r"(a[0]), "r"(a[1]), "r"(a[2]), "r"(a[3]), "r"(b0), "r"(b1));
}

// ---------------- prep A: fp32 -> fp16 ----------------
__global__ __launch_bounds__(256)
void prep_a(const float* __restrict__ x, const float* __restrict__ h) {
    int gid = blockIdx.x * 256 + threadIdx.x;      // 8 elems per thread
    int m = gid >> 7;
    int k8 = (gid & 127) << 3;
    const float* s = (k8 < 512) ? (x + (size_t)m * 512 + k8)
                                : (h + (size_t)m * 512 + (k8 - 512));
    float4 v0 = ((const float4*)s)[0];
    float4 v1 = ((const float4*)s)[1];
    __half hh[8];
    hh[0] = __float2half_rn(v0.x); hh[1] = __float2half_rn(v0.y);
    hh[2] = __float2half_rn(v0.z); hh[3] = __float2half_rn(v0.w);
    hh[4] = __float2half_rn(v1.x); hh[5] = __float2half_rn(v1.y);
    hh[6] = __float2half_rn(v1.z); hh[7] = __float2half_rn(v1.w);
    *(uint4*)(g_A + (size_t)m * 2048 + (size_t)k8 * 2) = *(uint4*)hh;
}

// ---------------- prep B: transpose + fp16 hi/lo split ----------------
__global__ void prep_b(const float* __restrict__ Wxi, const float* __restrict__ Whi,
                       const float* __restrict__ Wxc, const float* __restrict__ Whc,
                       const float* __restrict__ Wxo, const float* __restrict__ Who) {
    __shared__ float tile[32][33];
    int n0 = blockIdx.x * 32;       // 0..1535
    int k0 = blockIdx.y * 32;       // 0..1023
    int g = n0 >> 9;
    int nc0 = n0 & 511;
    const float* Wx = (g == 0) ? Wxi : ((g == 1) ? Wxc : Wxo);
    const float* Wh = (g == 0) ? Whi : ((g == 1) ? Whc : Who);
    int tx = threadIdx.x, ty = threadIdx.y;   // 32 x 8
    #pragma unroll
    for (int r = ty; r < 32; r += 8) {
        int k = k0 + r;
        const float* W = (k < 512) ? (Wx + (size_t)k * 512) : (Wh + (size_t)(k - 512) * 512);
        tile[r][tx] = W[nc0 + tx];
    }
    __syncthreads();
    #pragma unroll
    for (int r = ty; r < 32; r += 8) {
        float v = tile[tx][r];                 // W[k0+tx][n0+r]
        __half hi = __float2half_rn(v);
        __half lo = __float2half_rn(v - __half2float(hi));
        int k = k0 + tx;
        unsigned char* dst = g_B + (size_t)(n0 + r) * 4096 + (size_t)(k >> 5) * 128 + (k & 31) * 2;
        *(__half*)dst        = hi;
        *(__half*)(dst + 64) = lo;
    }
}

// ---------------- fused GEMM + epilogue ----------------
// CTA 128m x 128n x 3 gates; 256 threads = 8 warps (2m x 4n), warp 64x32/gate.
// Stage (k32): A 8KB (128 rows x 64B, SW64) + B 48KB (384 rows x [hi64|lo64], SW128).
// 3 stages = 168KB.
#define STAGE_BYTES 57344u
__global__ __launch_bounds__(256, 1)
void lstm_gemm(const float* __restrict__ bxi, const float* __restrict__ bxc,
               const float* __restrict__ bxo,
               float* __restrict__ outh, float* __restrict__ outc) {
    extern __shared__ char dsm[];
    const uint32_t s0 = (smem_u32(dsm) + 1023) & ~1023u;

    const int tid  = threadIdx.x;
    const int lane = tid & 31;
    const int wid  = tid >> 5;
    const int wm   = wid >> 2;       // 0..1 -> m offset 64*wm
    const int wn   = wid & 3;        // 0..3 -> n offset 32*wn
    const int m0   = blockIdx.y << 7;
    const int n0   = blockIdx.x << 7;

    // A ldmatrix bases (SW64): row*64 + (lane>>4)*16; per-mt add 16 rows; per-ks XOR 32
    uint32_t a_base[4];
    #pragma unroll
    for (int mt = 0; mt < 4; ++mt) {
        int row = (wm << 6) + (mt << 4) + (lane & 15);
        int ro  = row * 64 + ((lane >> 4) << 4);
        a_base[mt] = SWZ64(ro);
    }
    // B ldmatrix bases (SW128): per-ks XOR 32, lo-half XOR 64, gate add g<<14
    uint32_t b_base[2];
    #pragma unroll
    for (int ng = 0; ng < 2; ++ng) {
        int rr = (wn << 5) + (ng << 4) + (lane & 7) + (((lane >> 4) & 1) << 3);
        int ro = (rr << 7) + (((lane >> 3) & 1) << 4);
        b_base[ng] = SWZ(ro);
    }

    float c[3][4][4][4];   // gate, mt, nt, e
    #pragma unroll
    for (int g = 0; g < 3; ++g)
        #pragma unroll
        for (int mt = 0; mt < 4; ++mt)
            #pragma unroll
            for (int nt = 0; nt < 4; ++nt)
                #pragma unroll
                for (int e = 0; e < 4; ++e) c[g][mt][nt][e] = 0.0f;

    // stage loader: A 512 + B 3072 = 3584 x 16B chunks, 14 per thread
    auto load_stage = [&](int s, int kc) {
        const uint32_t sa = s0 + (uint32_t)s * STAGE_BYTES;
        #pragma unroll
        for (int i = 0; i < 14; ++i) {
            int gid = tid + 256 * i;
            if (gid < 512) {
                int row = gid >> 2, grp = gid & 3;
                int ob = row * 64 + (grp << 4);
                cpa16(sa + SWZ64(ob),
                      g_A + (size_t)(m0 + row) * 2048 + (size_t)kc * 64 + (grp << 4));
            } else {
                int t = gid - 512;               // 0..3071
                int row = t >> 3, grp = t & 7;   // row = g*128 + n
                int g = row >> 7, n = row & 127;
                int ob = (row << 7) + (grp << 4);
                cpa16(sa + 8192u + SWZ(ob),
                      g_B + (size_t)((g << 9) + n0 + n) * 4096 + (size_t)kc * 128 + (grp << 4));
            }
        }
    };

    load_stage(0, 0);
    asm volatile("cp.async.commit_group;" ::: "memory");
    load_stage(1, 1);
    asm volatile("cp.async.commit_group;" ::: "memory");

    for (int kc = 0; kc < NKC; ++kc) {
        asm volatile("cp.async.wait_group 1;" ::: "memory");
        __syncthreads();
        if (kc + 2 < NKC) load_stage((kc + 2) % 3, kc + 2);
        asm volatile("cp.async.commit_group;" ::: "memory");

        const uint32_t sA = s0 + (uint32_t)(kc % 3) * STAGE_BYTES;
        const uint32_t sB = sA + 8192u;

        #pragma unroll
        for (int ks = 0; ks < 2; ++ks) {
            const uint32_t kx = (uint32_t)(ks << 5);
            uint32_t af[4][4];
            #pragma unroll
            for (int mt = 0; mt < 4; ++mt)
                ldmx4(af[mt], sA + (a_base[mt] ^ kx));
            #pragma unroll
            for (int g = 0; g < 3; ++g) {
                const uint32_t bb = sB + ((uint32_t)g << 14);
                #pragma unroll
                for (int ng = 0; ng < 2; ++ng) {
                    uint32_t bh[4], bl[4];
                    ldmx4(bh, bb + (b_base[ng] ^ kx));
                    ldmx4(bl, bb + (b_base[ng] ^ kx ^ 64u));
                    #pragma unroll
                    for (int mt = 0; mt < 4; ++mt) {
                        mma16816(c[g][mt][2*ng+0], af[mt], bh[0], bh[1]);
                        mma16816(c[g][mt][2*ng+1], af[mt], bh[2], bh[3]);
                        mma16816(c[g][mt][2*ng+0], af[mt], bl[0], bl[1]);
                        mma16816(c[g][mt][2*ng+1], af[mt], bl[2], bl[3]);
                    }
                }
            }
        }
    }

    // ---- fused epilogue ----
    const int ncb = n0 + (wn << 5) + ((lane & 3) << 1);
    float2 bi2[4], bc2[4], bo2[4];
    #pragma unroll
    for (int nt = 0; nt < 4; ++nt) {
        bi2[nt] = *(const float2*)(bxi + ncb + nt * 8);
        bc2[nt] = *(const float2*)(bxc + ncb + nt * 8);
        bo2[nt] = *(const float2*)(bxo + ncb + nt * 8);
    }

    #pragma unroll
    for (int mt = 0; mt < 4; ++mt) {
        #pragma unroll
        for (int half = 0; half < 2; ++half) {
            int m = m0 + (wm << 6) + (mt << 4) + (lane >> 2) + half * 8;
            size_t ob = (size_t)m * 512;
            #pragma unroll
            for (int nt = 0; nt < 4; ++nt) {
                float hv[2], cv[2];
                #pragma unroll
                for (int e = 0; e < 2; ++e) {
                    int idx = half * 2 + e;
                    float ip = c[0][mt][nt][idx] + (e ? bi2[nt].y : bi2[nt].x);
                    float cp = c[1][mt][nt][idx] + (e ? bc2[nt].y : bc2[nt].x);
                    float op = c[2][mt][nt][idx] + (e ? bo2[nt].y : bo2[nt].x);
                    float ig = 1.0f / (1.0f + __expf(-ip));
                    float og = 1.0f / (1.0f + __expf(-op));
                    float tc = 1.0f - 2.0f / (__expf(2.0f * cp) + 1.0f);
                    float cn = ig * tc;
                    float tn = 1.0f - 2.0f / (__expf(2.0f * cn) + 1.0f);
                    cv[e] = cn;
                    hv[e] = og * tn;
                }
                *(float2*)(outh + ob + ncb + nt * 8) = *(float2*)hv;
                *(float2*)(outc + ob + ncb + nt * 8) = *(float2*)cv;
            }
        }
    }
}

// ---------------- launcher ----------------
extern "C" void kernel_launch(void* const* d_in, const int* in_sizes, int n_in,
                              void* d_out, int out_size) {
    // 0:x 1:h 2:c_prev 3:Wxi 4:bxi 5:Whi 6:Wxf 7:bxf 8:Whf 9:Wxc 10:bxc 11:Whc 12:Wxo 13:bxo 14:Who
    const float* x   = (const float*)d_in[0];
    const float* h   = (const float*)d_in[1];
    const float* Wxi = (const float*)d_in[3];
    const float* bxi = (const float*)d_in[4];
    const float* Whi = (const float*)d_in[5];
    const float* Wxc = (const float*)d_in[9];
    const float* bxc = (const float*)d_in[10];
    const float* Whc = (const float*)d_in[11];
    const float* Wxo = (const float*)d_in[12];
    const float* bxo = (const float*)d_in[13];
    const float* Who = (const float*)d_in[14];

    float* outh = (float*)d_out;
    float* outc = outh + (size_t)M_SZ * H_SZ;

    cudaFuncSetAttribute(lstm_gemm, cudaFuncAttributeMaxDynamicSharedMemorySize,
                         3 * 57344 + 1024);

    prep_a<<<16384, 256>>>(x, h);
    prep_b<<<dim3(48, 32), dim3(32, 8)>>>(Wxi, Whi, Wxc, Whc, Wxo, Who);
    lstm_gemm<<<dim3(4, 256), 256, 3 * 57344 + 1024>>>(bxi, bxc, bxo, outh, outc);
}

// round 7
// speedup vs baseline: 2.0780x; 1.5435x over previous
#include <cuda_runtime.h>
#include <cuda_fp16.h>
#include <cstdint>

// ---------------- problem constants ----------------
#define M_SZ 32768
#define H_SZ 512
#define K_SZ 1024
#define NKC  32            // k32 chunks

#define SWZ64(x) ((uint32_t)(x) ^ ((((uint32_t)(x)) >> 3) & 0x30))

// A: fp16 [m][k], 2KB/row.  B: fp16 [gate*512+n][k], 2KB/row (k-major)
__device__ unsigned char g_A[(size_t)M_SZ * 2048];          // 64MB
__device__ unsigned char g_B[(size_t)3 * H_SZ * 2048];      // 3MB

// ---------------- helpers ----------------
__device__ __forceinline__ uint32_t smem_u32(const void* p) {
    uint32_t a;
    asm("{ .reg .u64 t; cvta.to.shared.u64 t, %1; cvt.u32.u64 %0, t; }" : "=r"(a) : "l"(p));
    return a;
}
__device__ __forceinline__ void cpa16(uint32_t d, const void* s) {
    asm volatile("cp.async.cg.shared.global [%0], [%1], 16;" :: "r"(d), "l"(s));
}
__device__ __forceinline__ void ldmx4(uint32_t* r, uint32_t a) {
    asm volatile("ldmatrix.sync.aligned.m8n8.x4.shared.b16 {%0,%1,%2,%3}, [%4];"
        : "=r"(r[0]), "=r"(r[1]), "=r"(r[2]), "=r"(r[3]) : "r"(a));
}
__device__ __forceinline__ void mma16816(float* c, const uint32_t* a, uint32_t b0, uint32_t b1) {
    asm volatile("mma.sync.aligned.m16n8k16.row.col.f32.f16.f16.f32 "
        "{%0,%1,%2,%3}, {%4,%5,%6,%7}, {%8,%9}, {%0,%1,%2,%3};"
        : "+f"(c[0]), "+f"(c[1]), "+f"(c[2]), "+f"(c[3])
        : "r"(a[0]), "r"(a[1]), "r"(a[2]), "r"(a[3]), "r"(b0), "r"(b1));
}

// ---------------- prep A: fp32 -> fp16 ----------------
__global__ __launch_bounds__(256)
void prep_a(const float* __restrict__ x, const float* __restrict__ h) {
    int gid = blockIdx.x * 256 + threadIdx.x;      // 8 elems per thread
    int m = gid >> 7;
    int k8 = (gid & 127) << 3;
    const float* s = (k8 < 512) ? (x + (size_t)m * 512 + k8)
                                : (h + (size_t)m * 512 + (k8 - 512));
    float4 v0 = ((const float4*)s)[0];
    float4 v1 = ((const float4*)s)[1];
    __half hh[8];
    hh[0] = __float2half_rn(v0.x); hh[1] = __float2half_rn(v0.y);
    hh[2] = __float2half_rn(v0.z); hh[3] = __float2half_rn(v0.w);
    hh[4] = __float2half_rn(v1.x); hh[5] = __float2half_rn(v1.y);
    hh[6] = __float2half_rn(v1.z); hh[7] = __float2half_rn(v1.w);
    *(uint4*)(g_A + (size_t)m * 2048 + (size_t)k8 * 2) = *(uint4*)hh;
}

// ---------------- prep B: transpose + fp16 ----------------
__global__ void prep_b(const float* __restrict__ Wxi, const float* __restrict__ Whi,
                       const float* __restrict__ Wxc, const float* __restrict__ Whc,
                       const float* __restrict__ Wxo, const float* __restrict__ Who) {
    __shared__ float tile[32][33];
    int n0 = blockIdx.x * 32;       // 0..1535
    int k0 = blockIdx.y * 32;       // 0..1023
    int g = n0 >> 9;
    int nc0 = n0 & 511;
    const float* Wx = (g == 0) ? Wxi : ((g == 1) ? Wxc : Wxo);
    const float* Wh = (g == 0) ? Whi : ((g == 1) ? Whc : Who);
    int tx = threadIdx.x, ty = threadIdx.y;   // 32 x 8
    #pragma unroll
    for (int r = ty; r < 32; r += 8) {
        int k = k0 + r;
        const float* W = (k < 512) ? (Wx + (size_t)k * 512) : (Wh + (size_t)(k - 512) * 512);
        tile[r][tx] = W[nc0 + tx];
    }
    __syncthreads();
    #pragma unroll
    for (int r = ty; r < 32; r += 8) {
        float v = tile[tx][r];                 // W[k0+tx][n0+r]
        *(__half*)(g_B + (size_t)(n0 + r) * 2048 + (size_t)(k0 + tx) * 2) = __float2half_rn(v);
    }
}

// ---------------- fused GEMM + epilogue ----------------
// CTA 128m x 128n x 3 gates; 256 threads = 8 warps (2m x 4n), warp 64x32/gate.
// Stage (k32): A 8KB + B 24KB = 32KB (SW64 rows of 64B); 4 stages = 128KB.
#define STAGE_BYTES 32768u
#define NSTAGE 4
__global__ __launch_bounds__(256, 1)
void lstm_gemm(const float* __restrict__ bxi, const float* __restrict__ bxc,
               const float* __restrict__ bxo,
               float* __restrict__ outh, float* __restrict__ outc) {
    extern __shared__ char dsm[];
    const uint32_t s0 = (smem_u32(dsm) + 1023) & ~1023u;

    const int tid  = threadIdx.x;
    const int lane = tid & 31;
    const int wid  = tid >> 5;
    const int wm   = wid >> 2;       // 0..1 -> m offset 64*wm
    const int wn   = wid & 3;        // 0..3 -> n offset 32*wn
    const int m0   = blockIdx.y << 7;
    const int n0   = blockIdx.x << 7;

    // A ldmatrix bases (SW64, 64B rows); per-ks XOR 32
    uint32_t a_base[4];
    #pragma unroll
    for (int mt = 0; mt < 4; ++mt) {
        int row = (wm << 6) + (mt << 4) + (lane & 15);
        int ro  = row * 64 + ((lane >> 4) << 4);
        a_base[mt] = SWZ64(ro);
    }
    // B ldmatrix bases (SW64, 64B rows); per-ks XOR 32; per-gate add g*8192
    uint32_t b_base[2];
    #pragma unroll
    for (int ng = 0; ng < 2; ++ng) {
        int rr = (wn << 5) + (ng << 4) + (lane & 7) + (((lane >> 4) & 1) << 3);
        int ro = rr * 64 + (((lane >> 3) & 1) << 4);
        b_base[ng] = SWZ64(ro);
    }

    float c[3][4][4][4];   // gate, mt, nt, e
    #pragma unroll
    for (int g = 0; g < 3; ++g)
        #pragma unroll
        for (int mt = 0; mt < 4; ++mt)
            #pragma unroll
            for (int nt = 0; nt < 4; ++nt)
                #pragma unroll
                for (int e = 0; e < 4; ++e) c[g][mt][nt][e] = 0.0f;

    // stage loader: A 512 + B 1536 = 2048 x 16B chunks, 8 per thread
    auto load_stage = [&](int s, int kc) {
        const uint32_t sa = s0 + (uint32_t)s * STAGE_BYTES;
        #pragma unroll
        for (int i = 0; i < 8; ++i) {
            int gid = tid + 256 * i;
            if (gid < 512) {
                int row = gid >> 2, grp = gid & 3;
                int ob = row * 64 + (grp << 4);
                cpa16(sa + SWZ64(ob),
                      g_A + (size_t)(m0 + row) * 2048 + (size_t)kc * 64 + (grp << 4));
            } else {
                int t = gid - 512;               // 0..1535
                int row = t >> 2, grp = t & 3;   // row = g*128 + n
                int g = row >> 7, n = row & 127;
                int ob = row * 64 + (grp << 4);
                cpa16(sa + 8192u + SWZ64(ob),
                      g_B + (size_t)((g << 9) + n0 + n) * 2048 + (size_t)kc * 64 + (grp << 4));
            }
        }
    };

    load_stage(0, 0);
    asm volatile("cp.async.commit_group;" ::: "memory");
    load_stage(1, 1);
    asm volatile("cp.async.commit_group;" ::: "memory");
    load_stage(2, 2);
    asm volatile("cp.async.commit_group;" ::: "memory");

    for (int kc = 0; kc < NKC; ++kc) {
        asm volatile("cp.async.wait_group 2;" ::: "memory");
        __syncthreads();
        if (kc + 3 < NKC) load_stage((kc + 3) % NSTAGE, kc + 3);
        asm volatile("cp.async.commit_group;" ::: "memory");

        const uint32_t sA = s0 + (uint32_t)(kc % NSTAGE) * STAGE_BYTES;
        const uint32_t sB = sA + 8192u;

        #pragma unroll
        for (int ks = 0; ks < 2; ++ks) {
            const uint32_t kx = (uint32_t)(ks << 5);
            uint32_t af[4][4];
            #pragma unroll
            for (int mt = 0; mt < 4; ++mt)
                ldmx4(af[mt], sA + (a_base[mt] ^ kx));
            #pragma unroll
            for (int g = 0; g < 3; ++g) {
                const uint32_t bb = sB + (uint32_t)(g * 8192);
                #pragma unroll
                for (int ng = 0; ng < 2; ++ng) {
                    uint32_t bh[4];
                    ldmx4(bh, bb + (b_base[ng] ^ kx));
                    #pragma unroll
                    for (int mt = 0; mt < 4; ++mt) {
                        mma16816(c[g][mt][2*ng+0], af[mt], bh[0], bh[1]);
                        mma16816(c[g][mt][2*ng+1], af[mt], bh[2], bh[3]);
                    }
                }
            }
        }
    }

    // ---- fused epilogue ----
    const int ncb = n0 + (wn << 5) + ((lane & 3) << 1);
    float2 bi2[4], bc2[4], bo2[4];
    #pragma unroll
    for (int nt = 0; nt < 4; ++nt) {
        bi2[nt] = *(const float2*)(bxi + ncb + nt * 8);
        bc2[nt] = *(const float2*)(bxc + ncb + nt * 8);
        bo2[nt] = *(const float2*)(bxo + ncb + nt * 8);
    }

    #pragma unroll
    for (int mt = 0; mt < 4; ++mt) {
        #pragma unroll
        for (int half = 0; half < 2; ++half) {
            int m = m0 + (wm << 6) + (mt << 4) + (lane >> 2) + half * 8;
            size_t ob = (size_t)m * 512;
            #pragma unroll
            for (int nt = 0; nt < 4; ++nt) {
                float hv[2], cv[2];
                #pragma unroll
                for (int e = 0; e < 2; ++e) {
                    int idx = half * 2 + e;
                    float ip = c[0][mt][nt][idx] + (e ? bi2[nt].y : bi2[nt].x);
                    float cp = c[1][mt][nt][idx] + (e ? bc2[nt].y : bc2[nt].x);
                    float op = c[2][mt][nt][idx] + (e ? bo2[nt].y : bo2[nt].x);
                    float ig = 1.0f / (1.0f + __expf(-ip));
                    float og = 1.0f / (1.0f + __expf(-op));
                    float tc = 1.0f - 2.0f / (__expf(2.0f * cp) + 1.0f);
                    float cn = ig * tc;
                    float tn = 1.0f - 2.0f / (__expf(2.0f * cn) + 1.0f);
                    cv[e] = cn;
                    hv[e] = og * tn;
                }
                *(float2*)(outh + ob + ncb + nt * 8) = *(float2*)hv;
                *(float2*)(outc + ob + ncb + nt * 8) = *(float2*)cv;
            }
        }
    }
}

// ---------------- launcher ----------------
extern "C" void kernel_launch(void* const* d_in, const int* in_sizes, int n_in,
                              void* d_out, int out_size) {
    // 0:x 1:h 2:c_prev 3:Wxi 4:bxi 5:Whi 6:Wxf 7:bxf 8:Whf 9:Wxc 10:bxc 11:Whc 12:Wxo 13:bxo 14:Who
    const float* x   = (const float*)d_in[0];
    const float* h   = (const float*)d_in[1];
    const float* Wxi = (const float*)d_in[3];
    const float* bxi = (const float*)d_in[4];
    const float* Whi = (const float*)d_in[5];
    const float* Wxc = (const float*)d_in[9];
    const float* bxc = (const float*)d_in[10];
    const float* Whc = (const float*)d_in[11];
    const float* Wxo = (const float*)d_in[12];
    const float* bxo = (const float*)d_in[13];
    const float* Who = (const float*)d_in[14];

    float* outh = (float*)d_out;
    float* outc = outh + (size_t)M_SZ * H_SZ;

    cudaFuncSetAttribute(lstm_gemm, cudaFuncAttributeMaxDynamicSharedMemorySize,
                         NSTAGE * 32768 + 1024);

    prep_a<<<16384, 256>>>(x, h);
    prep_b<<<dim3(48, 32), dim3(32, 8)>>>(Wxi, Whi, Wxc, Whc, Wxo, Who);
    lstm_gemm<<<dim3(4, 256), 256, NSTAGE * 32768 + 1024>>>(bxi, bxc, bxo, outh, outc);
}

// round 8
// speedup vs baseline: 2.3014x; 1.1075x over previous
#include <cuda_runtime.h>
#include <cuda_fp16.h>
#include <cstdint>

// ---------------- problem constants ----------------
#define M_SZ 32768
#define H_SZ 512
#define K_SZ 1024
#define NKC  32            // k32 chunks
#define NSTAGE 6
#define STAGE_BYTES 32768u

#define SWZ64(x) ((uint32_t)(x) ^ ((((uint32_t)(x)) >> 3) & 0x30))

// A: blocked+pre-swizzled: [m>>7][kc][ SWZ64((m&127)*64 + byte) ]  (8KB blocks)
// B: blocked+pre-swizzled: [kc][gate][n>>7][ SWZ64((n&127)*64 + byte) ] (8KB blocks)
__device__ __align__(128) unsigned char g_A[(size_t)M_SZ * 2048];          // 64MB
__device__ __align__(128) unsigned char g_B[(size_t)3 * H_SZ * 2048];      // 3MB

// ---------------- helpers ----------------
__device__ __forceinline__ uint32_t smem_u32(const void* p) {
    uint32_t a;
    asm("{ .reg .u64 t; cvta.to.shared.u64 t, %1; cvt.u32.u64 %0, t; }" : "=r"(a) : "l"(p));
    return a;
}
__device__ __forceinline__ void ldmx4(uint32_t* r, uint32_t a) {
    asm volatile("ldmatrix.sync.aligned.m8n8.x4.shared.b16 {%0,%1,%2,%3}, [%4];"
        : "=r"(r[0]), "=r"(r[1]), "=r"(r[2]), "=r"(r[3]) : "r"(a));
}
__device__ __forceinline__ void mma16816(float* c, const uint32_t* a, uint32_t b0, uint32_t b1) {
    asm volatile("mma.sync.aligned.m16n8k16.row.col.f32.f16.f16.f32 "
        "{%0,%1,%2,%3}, {%4,%5,%6,%7}, {%8,%9}, {%0,%1,%2,%3};"
        : "+f"(c[0]), "+f"(c[1]), "+f"(c[2]), "+f"(c[3])
        : "r"(a[0]), "r"(a[1]), "r"(a[2]), "r"(a[3]), "r"(b0), "r"(b1));
}
__device__ __forceinline__ void mbar_init(uint32_t a, uint32_t cnt) {
    asm volatile("mbarrier.init.shared.b64 [%0], %1;" :: "r"(a), "r"(cnt) : "memory");
}
__device__ __forceinline__ void mbar_expect_tx(uint32_t a, uint32_t tx) {
    asm volatile("mbarrier.arrive.expect_tx.shared.b64 _, [%0], %1;" :: "r"(a), "r"(tx) : "memory");
}
__device__ __forceinline__ void mbar_wait(uint32_t a, uint32_t parity) {
    asm volatile(
        "{\n\t.reg .pred P;\n\t"
        "WL%=:\n\t"
        "mbarrier.try_wait.parity.acquire.cta.shared::cta.b64 P, [%0], %1, 0x989680;\n\t"
        "@P bra WD%=;\n\t"
        "bra WL%=;\n\t"
        "WD%=:\n\t}"
        :: "r"(a), "r"(parity) : "memory");
}
__device__ __forceinline__ void bulk_g2s(uint32_t dst, const void* src, uint32_t bytes, uint32_t mbar) {
    asm volatile(
        "cp.async.bulk.shared::cluster.global.mbarrier::complete_tx::bytes [%0], [%1], %2, [%3];"
        :: "r"(dst), "l"(src), "r"(bytes), "r"(mbar) : "memory");
}

// ---------------- prep A: fp32 -> fp16, blocked + pre-swizzled ----------------
__global__ __launch_bounds__(256)
void prep_a(const float* __restrict__ x, const float* __restrict__ h) {
    int gid = blockIdx.x * 256 + threadIdx.x;      // 8 elems per thread
    int m = gid >> 7;
    int k8 = (gid & 127) << 3;
    const float* s = (k8 < 512) ? (x + (size_t)m * 512 + k8)
                                : (h + (size_t)m * 512 + (k8 - 512));
    float4 v0 = ((const float4*)s)[0];
    float4 v1 = ((const float4*)s)[1];
    __half hh[8];
    hh[0] = __float2half_rn(v0.x); hh[1] = __float2half_rn(v0.y);
    hh[2] = __float2half_rn(v0.z); hh[3] = __float2half_rn(v0.w);
    hh[4] = __float2half_rn(v1.x); hh[5] = __float2half_rn(v1.y);
    hh[6] = __float2half_rn(v1.z); hh[7] = __float2half_rn(v1.w);
    size_t blk = ((size_t)(m >> 7) * NKC + (k8 >> 5)) * 8192;
    uint32_t ob = SWZ64(((m & 127) << 6) + ((k8 & 31) << 1));
    *(uint4*)(g_A + blk + ob) = *(uint4*)hh;
}

// ---------------- prep B: transpose + fp16, blocked + pre-swizzled ----------------
__global__ void prep_b(const float* __restrict__ Wxi, const float* __restrict__ Whi,
                       const float* __restrict__ Wxc, const float* __restrict__ Whc,
                       const float* __restrict__ Wxo, const float* __restrict__ Who) {
    __shared__ float tile[32][33];
    int n0 = blockIdx.x * 32;       // 0..1535 (gate-major n)
    int k0 = blockIdx.y * 32;       // 0..1023
    int g = n0 >> 9;
    int nc0 = n0 & 511;
    const float* Wx = (g == 0) ? Wxi : ((g == 1) ? Wxc : Wxo);
    const float* Wh = (g == 0) ? Whi : ((g == 1) ? Whc : Who);
    int tx = threadIdx.x, ty = threadIdx.y;   // 32 x 8
    #pragma unroll
    for (int r = ty; r < 32; r += 8) {
        int k = k0 + r;
        const float* W = (k < 512) ? (Wx + (size_t)k * 512) : (Wh + (size_t)(k - 512) * 512);
        tile[r][tx] = W[nc0 + tx];
    }
    __syncthreads();
    #pragma unroll
    for (int r = ty; r < 32; r += 8) {
        float v = tile[tx][r];                 // W[k0+tx][n0+r]
        int n = nc0 + r;                       // 0..511 within gate
        int k = k0 + tx;
        size_t blk = ((size_t)((k >> 5) * 3 + g) * 4 + (n >> 7)) * 8192;
        uint32_t ob = SWZ64(((n & 127) << 6) + ((k & 31) << 1));
        *(__half*)(g_B + blk + ob) = __float2half_rn(v);
    }
}

// ---------------- fused GEMM + epilogue ----------------
// CTA 128m x 128n x 3 gates; 256 threads = 8 warps (2m x 4n), warp 64x32/gate.
// Stage (k32): [A 8KB][B0 8KB][B1 8KB][B2 8KB]; 6 stages; loads via cp.async.bulk.
__global__ __launch_bounds__(256, 1)
void lstm_gemm(const float* __restrict__ bxi, const float* __restrict__ bxc,
               const float* __restrict__ bxo,
               float* __restrict__ outh, float* __restrict__ outc) {
    extern __shared__ char dsm[];
    const uint32_t sb = (smem_u32(dsm) + 1023) & ~1023u;   // mbarriers
    const uint32_t sd = sb + 1024;                          // stage data

    const int tid  = threadIdx.x;
    const int lane = tid & 31;
    const int wid  = tid >> 5;
    const int wm   = wid >> 2;       // 0..1 -> m offset 64*wm
    const int wn   = wid & 3;        // 0..3 -> n offset 32*wn
    const int m0   = blockIdx.y << 7;
    const int n0   = blockIdx.x << 7;
    const int mb   = m0 >> 7;
    const int nb   = n0 >> 7;

    // mbarrier init
    if (tid == 0) {
        #pragma unroll
        for (int s = 0; s < NSTAGE; ++s) mbar_init(sb + 8 * s, 1);
        asm volatile("fence.proxy.async.shared::cta;" ::: "memory");
    }
    __syncthreads();

    // stage issuer (single thread)
    auto issue_stage = [&](int kc) {
        const int s = kc % NSTAGE;
        const uint32_t mbar = sb + 8 * s;
        const uint32_t dst = sd + (uint32_t)s * STAGE_BYTES;
        mbar_expect_tx(mbar, STAGE_BYTES);
        bulk_g2s(dst, g_A + ((size_t)mb * NKC + kc) * 8192, 8192u, mbar);
        #pragma unroll
        for (int g = 0; g < 3; ++g)
            bulk_g2s(dst + 8192u * (1 + g),
                     g_B + ((size_t)(kc * 3 + g) * 4 + nb) * 8192, 8192u, mbar);
    };

    if (tid == 0) {
        #pragma unroll
        for (int p = 0; p < 5; ++p) issue_stage(p);
    }

    // ldmatrix bases (SW64, 64B rows); per-ks XOR 32
    uint32_t a_base[4];
    #pragma unroll
    for (int mt = 0; mt < 4; ++mt) {
        int row = (wm << 6) + (mt << 4) + (lane & 15);
        int ro  = row * 64 + ((lane >> 4) << 4);
        a_base[mt] = SWZ64(ro);
    }
    uint32_t b_base[2];
    #pragma unroll
    for (int ng = 0; ng < 2; ++ng) {
        int rr = (wn << 5) + (ng << 4) + (lane & 7) + (((lane >> 4) & 1) << 3);
        int ro = rr * 64 + (((lane >> 3) & 1) << 4);
        b_base[ng] = SWZ64(ro);
    }

    float c[3][4][4][4];   // gate, mt, nt, e
    #pragma unroll
    for (int g = 0; g < 3; ++g)
        #pragma unroll
        for (int mt = 0; mt < 4; ++mt)
            #pragma unroll
            for (int nt = 0; nt < 4; ++nt)
                #pragma unroll
                for (int e = 0; e < 4; ++e) c[g][mt][nt][e] = 0.0f;

    for (int kc = 0; kc < NKC; ++kc) {
        const int s = kc % NSTAGE;
        mbar_wait(sb + 8 * s, (kc / NSTAGE) & 1);

        const uint32_t sA = sd + (uint32_t)s * STAGE_BYTES;

        #pragma unroll
        for (int ks = 0; ks < 2; ++ks) {
            const uint32_t kx = (uint32_t)(ks << 5);
            uint32_t af[4][4];
            #pragma unroll
            for (int mt = 0; mt < 4; ++mt)
                ldmx4(af[mt], sA + (a_base[mt] ^ kx));
            #pragma unroll
            for (int g = 0; g < 3; ++g) {
                const uint32_t bb = sA + 8192u * (1 + g);
                #pragma unroll
                for (int ng = 0; ng < 2; ++ng) {
                    uint32_t bh[4];
                    ldmx4(bh, bb + (b_base[ng] ^ kx));
                    #pragma unroll
                    for (int mt = 0; mt < 4; ++mt) {
                        mma16816(c[g][mt][2*ng+0], af[mt], bh[0], bh[1]);
                        mma16816(c[g][mt][2*ng+1], af[mt], bh[2], bh[3]);
                    }
                }
            }
        }

        __syncthreads();
        if (tid == 0 && kc + 5 < NKC) issue_stage(kc + 5);
    }

    // ---- fused epilogue ----
    const int ncb = n0 + (wn << 5) + ((lane & 3) << 1);
    float2 bi2[4], bc2[4], bo2[4];
    #pragma unroll
    for (int nt = 0; nt < 4; ++nt) {
        bi2[nt] = *(const float2*)(bxi + ncb + nt * 8);
        bc2[nt] = *(const float2*)(bxc + ncb + nt * 8);
        bo2[nt] = *(const float2*)(bxo + ncb + nt * 8);
    }

    #pragma unroll
    for (int mt = 0; mt < 4; ++mt) {
        #pragma unroll
        for (int half = 0; half < 2; ++half) {
            int m = m0 + (wm << 6) + (mt << 4) + (lane >> 2) + half * 8;
            size_t ob = (size_t)m * 512;
            #pragma unroll
            for (int nt = 0; nt < 4; ++nt) {
                float hv[2], cv[2];
                #pragma unroll
                for (int e = 0; e < 2; ++e) {
                    int idx = half * 2 + e;
                    float ip = c[0][mt][nt][idx] + (e ? bi2[nt].y : bi2[nt].x);
                    float cp = c[1][mt][nt][idx] + (e ? bc2[nt].y : bc2[nt].x);
                    float op = c[2][mt][nt][idx] + (e ? bo2[nt].y : bo2[nt].x);
                    float ig = 1.0f / (1.0f + __expf(-ip));
                    float og = 1.0f / (1.0f + __expf(-op));
                    float tc = 1.0f - 2.0f / (__expf(2.0f * cp) + 1.0f);
                    float cn = ig * tc;
                    float tn = 1.0f - 2.0f / (__expf(2.0f * cn) + 1.0f);
                    cv[e] = cn;
                    hv[e] = og * tn;
                }
                *(float2*)(outh + ob + ncb + nt * 8) = *(float2*)hv;
                *(float2*)(outc + ob + ncb + nt * 8) = *(float2*)cv;
            }
        }
    }
}

// ---------------- launcher ----------------
extern "C" void kernel_launch(void* const* d_in, const int* in_sizes, int n_in,
                              void* d_out, int out_size) {
    // 0:x 1:h 2:c_prev 3:Wxi 4:bxi 5:Whi 6:Wxf 7:bxf 8:Whf 9:Wxc 10:bxc 11:Whc 12:Wxo 13:bxo 14:Who
    const float* x   = (const float*)d_in[0];
    const float* h   = (const float*)d_in[1];
    const float* Wxi = (const float*)d_in[3];
    const float* bxi = (const float*)d_in[4];
    const float* Whi = (const float*)d_in[5];
    const float* Wxc = (const float*)d_in[9];
    const float* bxc = (const float*)d_in[10];
    const float* Whc = (const float*)d_in[11];
    const float* Wxo = (const float*)d_in[12];
    const float* bxo = (const float*)d_in[13];
    const float* Who = (const float*)d_in[14];

    float* outh = (float*)d_out;
    float* outc = outh + (size_t)M_SZ * H_SZ;

    const int smem = 2048 + NSTAGE * (int)STAGE_BYTES;   // ctrl + stages
    cudaFuncSetAttribute(lstm_gemm, cudaFuncAttributeMaxDynamicSharedMemorySize, smem);

    prep_a<<<16384, 256>>>(x, h);
    prep_b<<<dim3(48, 32), dim3(32, 8)>>>(Wxi, Whi, Wxc, Whc, Wxo, Who);
    lstm_gemm<<<dim3(4, 256), 256, smem>>>(bxi, bxc, bxo, outh, outc);
}